// round 6
// baseline (speedup 1.0000x reference)
#include <cuda_runtime.h>
#include <cuda_bf16.h>
#include <cstdint>

// Problem shape (BGEM3 sparse-embedding head)
#define BB 32
#define SS 1024
#define HH 1024
#define VV 250002

#define ROWS      (BB * SS)          // 32768
#define OUT_ELEMS (BB * VV)          // 8000064
#define OUT_F4    (OUT_ELEMS / 4)    // 2000016

#define CBLOCKS   4096               // compute blocks: 8 warps * 1 row/warp

// Output is split into 16384-element (64 KB) regions; one bin per region.
#define REGION_LOG2 14
#define REGION    (1 << REGION_LOG2)             // 16384 floats
#define NBINS     ((OUT_ELEMS + REGION - 1) / REGION)   // 489
// A region spans < V, so it intersects at most 2 batches; each batch has
// 1024 rows -> at most 2048 entries can ever land in one bin. No overflow.
#define CAP       2048

// Per-bin entry lists. g_cnt starts 0 (static init) and is reset to 0 by
// kernel 2 every call -> deterministic across graph replays.
__device__ int  g_cnt[NBINS];
__device__ int2 g_ent[NBINS * CAP];   // (.x = offset within region, .y = f32 bits)

// ---------------------------------------------------------------------------
// Kernel 1: pure-read GEMV + ReLU + binning. One warp per hidden row.
// ---------------------------------------------------------------------------
__global__ __launch_bounds__(256) void bgem3_dot_bin(
    const float4* __restrict__ hidden,   // [B*S, H/4]
    const int*    __restrict__ ids,      // [B*S]
    const float4* __restrict__ W4,       // [H/4]
    const float*  __restrict__ bias)     // [1]
{
    const int tid = threadIdx.x;

    __shared__ float4 w[HH / 4];  // 4 KB
    w[tid] = W4[tid];
    __syncthreads();

    const int warp = tid >> 5;
    const int lane = tid & 31;
    const int row  = blockIdx.x * 8 + warp;      // [0, ROWS)

    const float4* h = hidden + (size_t)row * (HH / 4);

    float sum = 0.0f;
#pragma unroll
    for (int i = 0; i < 8; i++) {
        const int idx = lane + i * 32;
        const float4 hv = h[idx];
        const float4 wv = w[idx];
        sum += hv.x * wv.x + hv.y * wv.y + hv.z * wv.z + hv.w * wv.w;
    }
#pragma unroll
    for (int off = 16; off > 0; off >>= 1)
        sum += __shfl_xor_sync(0xFFFFFFFFu, sum, off);

    if (lane == 0) {
        const float tw = sum + bias[0];
        const int token = ids[row];
        // tokens 0..3 are masked to zero in the reference; the table is
        // zero-filled by kernel 2, so skipping them is equivalent.
        if (tw > 0.0f && token >= 4) {
            const int b    = row >> 10;                 // row / SS
            const int addr = b * VV + token;            // < 8000064, fits int
            const int bin  = addr >> REGION_LOG2;
            const int pos  = atomicAdd(&g_cnt[bin], 1);
            g_ent[bin * CAP + pos] =
                make_int2(addr & (REGION - 1), __float_as_int(tw));
        }
    }
}

// ---------------------------------------------------------------------------
// Kernel 2: one block per region. Zero the region, then apply this bin's
// entries (ordering vs own zeros guaranteed by __syncthreads' block-scope
// memory fence), then reset the counter for the next replay.
// ---------------------------------------------------------------------------
__global__ __launch_bounds__(256) void bgem3_zero_apply(
    float* __restrict__ out)     // [B*V]
{
    const int bin = blockIdx.x;
    const int tid = threadIdx.x;

    // ---- zero phase: 16384 floats = 4096 float4, 16 per thread ----
    float4* out4 = (float4*)out;
    const int base4 = bin * (REGION / 4);
    const float4 z = make_float4(0.f, 0.f, 0.f, 0.f);
#pragma unroll
    for (int i = 0; i < 16; i++) {
        const int idx = base4 + tid + i * 256;
        if (idx < OUT_F4) out4[idx] = z;
    }
    __syncthreads();   // orders this block's zero stores before its atomics

    // ---- apply phase ----
    const int cnt  = g_cnt[bin];
    const int base = bin << REGION_LOG2;
    for (int e = tid; e < cnt; e += 256) {
        const int2 ent = g_ent[bin * CAP + e];
        // post-ReLU weights >= 0, region just zeroed -> IEEE-754 bits are
        // monotone as signed int: integer atomicMax == exact float max.
        atomicMax(reinterpret_cast<int*>(out) + base + ent.x, ent.y);
    }

    __syncthreads();
    if (tid == 0) g_cnt[bin] = 0;   // reset for next graph replay
}

extern "C" void kernel_launch(void* const* d_in, const int* in_sizes, int n_in,
                              void* d_out, int out_size)
{
    const float4* hidden = (const float4*)d_in[0];  // [B,S,H] f32
    const int*    ids    = (const int*)d_in[1];     // [B,S] i32
    const float4* W4     = (const float4*)d_in[2];  // [1,H] f32
    const float*  bias   = (const float*)d_in[3];   // [1] f32
    float*        out    = (float*)d_out;           // [B,V] f32

    bgem3_dot_bin<<<CBLOCKS, 256>>>(hidden, ids, W4, bias);
    bgem3_zero_apply<<<NBINS, 256>>>(out);
}